// round 9
// baseline (speedup 1.0000x reference)
#include <cuda_runtime.h>
#include <cstddef>

// Problem constants (fixed by the dataset problem)
#define CC 32
#define HH 128
#define WW 512
#define PAD 40
#define DD (PAD + 1)

// out[c,d,h,w] = in1[c,h,w] * (w >= d ? in2[c,h,w-d] : 0)
//
// One CTA per (c,h) row (4096 CTAs, 128 threads). in2 row staged once into
// shared memory with a PAD-float zero apron. Thread t owns the aligned float4
// at w = 4t. The shifted in2 window slides one float left per disparity via
// the shuffle network (thread t's next b0 = thread t-1's current b3); only
// lane 0 reads shared in the loop, so in-loop L1tex traffic is stores-only.
//
// Stores are write-through (__stwt): output lines are write-once/never-read
// and fully covered (each warp writes four full 128B lines per store), so
// pushing them straight toward DRAM avoids dirty-line accumulation in L2 and
// keeps the write queue smoothly fed. No launch_bounds cap: the occupancy
// experiment (R7) showed >61% occupancy slightly HURTS drain efficiency.
__global__ __launch_bounds__(128) void corr1d_row_kernel(
    const float* __restrict__ in1,
    const float* __restrict__ in2,
    float* __restrict__ out)
{
    __shared__ float s2[PAD + WW];   // 552 floats; [0,PAD) is the zero apron

    const int row  = blockIdx.x;     // (c,h) in [0, C*H)
    const int t    = threadIdx.x;    // 0..127
    const int lane = t & 31;
    const int c    = row / HH;
    const int h    = row % HH;

    // Stage rows. PAD*4 = 160 bytes, 16B-aligned, so float4 stores into
    // s2+PAD are legal.
    const float4 a = reinterpret_cast<const float4*>(in1 + (size_t)row * WW)[t];
    if (t < PAD) s2[t] = 0.0f;
    reinterpret_cast<float4*>(s2 + PAD)[t] =
        reinterpret_cast<const float4*>(in2 + (size_t)row * WW)[t];
    __syncthreads();

    // Output base for d=0 plane of this (c,h) row; planes are HH*WW apart.
    float4* po = reinterpret_cast<float4*>(
        out + ((size_t)(c * DD) * HH + h) * WW) + t;
    const size_t plane_stride_v4 = (size_t)HH * WW / 4;   // 16384 float4s

    // d=0 window: one aligned LDS.128.
    float4 b = reinterpret_cast<const float4*>(s2 + PAD)[t];
    float b0 = b.x, b1 = b.y, b2 = b.z, b3 = b.w;

    const int base = PAD + 4 * t;    // s2 index of b0 at d=0

    #pragma unroll
    for (int d = 0; d <= PAD; ++d) {
        float4 r;
        r.x = a.x * b0;
        r.y = a.y * b1;
        r.z = a.z * b2;
        r.w = a.w * b3;
        __stwt(po + (size_t)d * plane_stride_v4, r);   // write-through store

        if (d < PAD) {
            // Next b0 = s2[base - d - 1] = previous lane's current b3.
            float carry = __shfl_up_sync(0xffffffffu, b3, 1);
            if (lane == 0) carry = s2[base - d - 1];   // warp-boundary fill
            b3 = b2;
            b2 = b1;
            b1 = b0;
            b0 = carry;
        }
    }
}

extern "C" void kernel_launch(void* const* d_in, const int* in_sizes, int n_in,
                              void* d_out, int out_size)
{
    const float* in1 = (const float*)d_in[0];
    const float* in2 = (const float*)d_in[1];
    float* out = (float*)d_out;

    corr1d_row_kernel<<<CC * HH, WW / 4>>>(in1, in2, out);
}

// round 10
// speedup vs baseline: 1.1171x; 1.1171x over previous
#include <cuda_runtime.h>
#include <cstddef>

// Problem constants (fixed by the dataset problem)
#define CC 32
#define HH 128
#define WW 512
#define PAD 40
#define DD (PAD + 1)

// out[c,d,h,w] = in1[c,h,w] * (w >= d ? in2[c,h,w-d] : 0)
//
// One CTA per (c,h) row (4096 CTAs, 128 threads). in2 row staged once into
// shared memory with a PAD-float zero apron. Thread t owns the aligned float4
// at w = 4t; the shifted in2 window lives in 4 rotating registers.
//
// d-loop unrolled by 2: from one window state (b0..b3 = W[base-d..base+3-d])
// we store plane d AND plane d+1 (which needs only carry1 = prev-lane b3),
// then advance the window by 2 via two INDEPENDENT shuffles (prev-lane b2 and
// b3, issued in parallel). This halves the per-plane SHFL(26cyc) dependency
// chain that gates store issue within a warp. Only lane 0 touches shared in
// the loop (conflict-free apron reads). Stores are evict-first streaming
// (__stcs) — the write-through experiment (R9) regressed.
__global__ __launch_bounds__(128) void corr1d_row_kernel(
    const float* __restrict__ in1,
    const float* __restrict__ in2,
    float* __restrict__ out)
{
    __shared__ float s2[PAD + WW];   // 552 floats; [0,PAD) is the zero apron

    const int row  = blockIdx.x;     // (c,h) in [0, C*H)
    const int t    = threadIdx.x;    // 0..127
    const int lane = t & 31;
    const int c    = row / HH;
    const int h    = row % HH;

    // Stage rows. PAD*4 = 160 bytes, 16B-aligned, so float4 stores into
    // s2+PAD are legal.
    const float4 a = reinterpret_cast<const float4*>(in1 + (size_t)row * WW)[t];
    if (t < PAD) s2[t] = 0.0f;
    reinterpret_cast<float4*>(s2 + PAD)[t] =
        reinterpret_cast<const float4*>(in2 + (size_t)row * WW)[t];
    __syncthreads();

    // Output base for d=0 plane of this (c,h) row; planes are HH*WW apart.
    float4* po = reinterpret_cast<float4*>(
        out + ((size_t)(c * DD) * HH + h) * WW) + t;
    const size_t plane_stride_v4 = (size_t)HH * WW / 4;   // 16384 float4s

    // d=0 window: one aligned LDS.128.
    float4 b = reinterpret_cast<const float4*>(s2 + PAD)[t];
    float b0 = b.x, b1 = b.y, b2 = b.z, b3 = b.w;

    const int base = PAD + 4 * t;    // s2 index of b0 at d=0

    #pragma unroll
    for (int d = 0; d < PAD; d += 2) {
        // Fetch both carries up front (independent shuffles, issued in
        // parallel; 26-cyc latency covers the two stores below).
        float carry0 = __shfl_up_sync(0xffffffffu, b2, 1);  // W[base-d-2]
        float carry1 = __shfl_up_sync(0xffffffffu, b3, 1);  // W[base-d-1]
        if (lane == 0) {
            carry0 = s2[base - d - 2];   // warp-boundary fill (apron-safe)
            carry1 = s2[base - d - 1];
        }

        // Plane d: window (b0, b1, b2, b3).
        float4 r0;
        r0.x = a.x * b0;
        r0.y = a.y * b1;
        r0.z = a.z * b2;
        r0.w = a.w * b3;
        __stcs(po + (size_t)d * plane_stride_v4, r0);

        // Plane d+1: window (carry1, b0, b1, b2).
        float4 r1;
        r1.x = a.x * carry1;
        r1.y = a.y * b0;
        r1.z = a.z * b1;
        r1.w = a.w * b2;
        __stcs(po + (size_t)(d + 1) * plane_stride_v4, r1);

        // Advance window by 2 disparities.
        b3 = b1;
        b2 = b0;
        b1 = carry1;
        b0 = carry0;
    }

    // Final plane d = PAD (window now at d = PAD).
    float4 r;
    r.x = a.x * b0;
    r.y = a.y * b1;
    r.z = a.z * b2;
    r.w = a.w * b3;
    __stcs(po + (size_t)PAD * plane_stride_v4, r);
}

extern "C" void kernel_launch(void* const* d_in, const int* in_sizes, int n_in,
                              void* d_out, int out_size)
{
    const float* in1 = (const float*)d_in[0];
    const float* in2 = (const float*)d_in[1];
    float* out = (float*)d_out;

    corr1d_row_kernel<<<CC * HH, WW / 4>>>(in1, in2, out);
}